// round 3
// baseline (speedup 1.0000x reference)
#include <cuda_runtime.h>
#include <math.h>

// Problem constants
#define MROWS 4096      // B*N = 2*2048
#define CDIM  1024
#define QKVD  3072
#define HID   4096
#define SEQ   2048
#define NHEAD 16
#define HD    64

// ---------------- scratch (device globals: allocation-free) ----------------
__device__ float g_y  [MROWS * (size_t)CDIM];  // ln1 output
__device__ float g_qkv[MROWS * (size_t)QKVD];  // qkv projections
__device__ float g_att[MROWS * (size_t)CDIM];  // attention output (pre-proj)
__device__ float g_x1 [MROWS * (size_t)CDIM];  // x + attn residual
__device__ float g_h  [MROWS * (size_t)CDIM];  // ln2 output
__device__ float g_f1 [MROWS * (size_t)HID];   // gelu(fc1) output

// ---------------- LayerNorm: one block per row of 1024 ----------------
__global__ void ln_kernel(const float* __restrict__ x,
                          const float* __restrict__ g,
                          const float* __restrict__ b,
                          float* __restrict__ y) {
    __shared__ float red[64];
    const int row = blockIdx.x;
    const int tid = threadIdx.x;  // 256 threads, 4 floats each
    const float4 v = reinterpret_cast<const float4*>(x + (size_t)row * CDIM)[tid];
    float s  = v.x + v.y + v.z + v.w;
    float sq = v.x * v.x + v.y * v.y + v.z * v.z + v.w * v.w;
    #pragma unroll
    for (int m = 16; m; m >>= 1) {
        s  += __shfl_xor_sync(0xffffffffu, s,  m);
        sq += __shfl_xor_sync(0xffffffffu, sq, m);
    }
    const int warp = tid >> 5, lane = tid & 31;
    if (lane == 0) { red[warp] = s; red[warp + 8] = sq; }
    __syncthreads();
    if (tid < 32) {
        float a = (tid < 8) ? red[tid] : 0.f;
        float c = (tid < 8) ? red[tid + 8] : 0.f;
        #pragma unroll
        for (int m = 4; m; m >>= 1) {
            a += __shfl_xor_sync(0xffffffffu, a, m);
            c += __shfl_xor_sync(0xffffffffu, c, m);
        }
        if (tid == 0) { red[0] = a; red[1] = c; }
    }
    __syncthreads();
    const float mean = red[0] * (1.f / CDIM);
    const float var  = red[1] * (1.f / CDIM) - mean * mean;
    const float rstd = rsqrtf(var + 1e-5f);
    const float4 gv = reinterpret_cast<const float4*>(g)[tid];
    const float4 bv = reinterpret_cast<const float4*>(b)[tid];
    float4 o;
    o.x = (v.x - mean) * rstd * gv.x + bv.x;
    o.y = (v.y - mean) * rstd * gv.y + bv.y;
    o.z = (v.z - mean) * rstd * gv.z + bv.z;
    o.w = (v.w - mean) * rstd * gv.w + bv.w;
    reinterpret_cast<float4*>(y + (size_t)row * CDIM)[tid] = o;
}

// ---------------- GEMM NT: C[M,N] = A[M,K] @ W[N,K]^T (+bias, epilogue) ----
// EPI: 0 = none, 1 = exact GELU, 2 = residual add
// Microtile is split 4+4 with a 64-offset (rows wm*4+i / 64+wm*4+i, cols
// wn*4+j / 64+wn*4+j) so the 16B-bank index within each 8-lane phase group is
// wn mod 8 (distinct) -> conflict-free B reads; A reads are broadcast.
template <int EPI>
__global__ __launch_bounds__(256, 2)
void gemm_nt(const float* __restrict__ A, const float* __restrict__ W,
             const float* __restrict__ bias, const float* __restrict__ res,
             float* __restrict__ Cout, int M, int N, int K) {
    __shared__ float As[16][132];  // k-major, padded: 528B row = 33*16B aligned
    __shared__ float Bs[16][132];
    const int bm = blockIdx.y * 128;
    const int bn = blockIdx.x * 128;
    const int tid = threadIdx.x;
    const int lr = tid >> 2;   // loader row 0..63
    const int lc = tid & 3;    // loader k-chunk 0..3
    const int wm = tid >> 4;   // compute m-group 0..15
    const int wn = tid & 15;   // compute n-group 0..15

    float acc[8][8];
    #pragma unroll
    for (int i = 0; i < 8; i++)
        #pragma unroll
        for (int j = 0; j < 8; j++) acc[i][j] = 0.f;

    const float* Ap0 = A + (size_t)(bm + lr) * K + lc * 4;
    const float* Ap1 = Ap0 + (size_t)64 * K;
    const float* Wp0 = W + (size_t)(bn + lr) * K + lc * 4;
    const float* Wp1 = Wp0 + (size_t)64 * K;

    // register prefetch of first k-slice
    float4 a0 = *(const float4*)(Ap0);
    float4 a1 = *(const float4*)(Ap1);
    float4 b0 = *(const float4*)(Wp0);
    float4 b1 = *(const float4*)(Wp1);

    for (int k0 = 0; k0 < K; k0 += 16) {
        __syncthreads();  // previous compute done reading smem
        As[lc * 4 + 0][lr]      = a0.x; As[lc * 4 + 1][lr]      = a0.y;
        As[lc * 4 + 2][lr]      = a0.z; As[lc * 4 + 3][lr]      = a0.w;
        As[lc * 4 + 0][lr + 64] = a1.x; As[lc * 4 + 1][lr + 64] = a1.y;
        As[lc * 4 + 2][lr + 64] = a1.z; As[lc * 4 + 3][lr + 64] = a1.w;
        Bs[lc * 4 + 0][lr]      = b0.x; Bs[lc * 4 + 1][lr]      = b0.y;
        Bs[lc * 4 + 2][lr]      = b0.z; Bs[lc * 4 + 3][lr]      = b0.w;
        Bs[lc * 4 + 0][lr + 64] = b1.x; Bs[lc * 4 + 1][lr + 64] = b1.y;
        Bs[lc * 4 + 2][lr + 64] = b1.z; Bs[lc * 4 + 3][lr + 64] = b1.w;
        __syncthreads();
        if (k0 + 16 < K) {  // prefetch next slice while computing this one
            a0 = *(const float4*)(Ap0 + k0 + 16);
            a1 = *(const float4*)(Ap1 + k0 + 16);
            b0 = *(const float4*)(Wp0 + k0 + 16);
            b1 = *(const float4*)(Wp1 + k0 + 16);
        }
        #pragma unroll
        for (int k = 0; k < 16; k++) {
            const float4 x0 = *(const float4*)&As[k][wm * 4];
            const float4 x1 = *(const float4*)&As[k][64 + wm * 4];
            const float4 y0 = *(const float4*)&Bs[k][wn * 4];
            const float4 y1 = *(const float4*)&Bs[k][64 + wn * 4];
            const float av[8] = {x0.x, x0.y, x0.z, x0.w, x1.x, x1.y, x1.z, x1.w};
            const float bv[8] = {y0.x, y0.y, y0.z, y0.w, y1.x, y1.y, y1.z, y1.w};
            #pragma unroll
            for (int i = 0; i < 8; i++)
                #pragma unroll
                for (int j = 0; j < 8; j++)
                    acc[i][j] += av[i] * bv[j];
        }
    }

    // epilogue: columns are bn+wn*4+j (j<4) and bn+64+wn*4+j-4 (j>=4)
    float bcol[8];
    #pragma unroll
    for (int j = 0; j < 8; j++) {
        const int col = bn + ((j < 4) ? (wn * 4 + j) : (64 + wn * 4 + j - 4));
        bcol[j] = bias ? bias[col] : 0.f;
    }

    #pragma unroll
    for (int i = 0; i < 8; i++) {
        const int r = bm + ((i < 4) ? (wm * 4 + i) : (64 + wm * 4 + i - 4));
        float* c0 = Cout + (size_t)r * N + bn + wn * 4;
        float v[8];
        #pragma unroll
        for (int j = 0; j < 8; j++) v[j] = acc[i][j] + bcol[j];
        if (EPI == 1) {
            #pragma unroll
            for (int j = 0; j < 8; j++)
                v[j] = 0.5f * v[j] * (1.f + erff(v[j] * 0.70710678118654752f));
        } else if (EPI == 2) {
            const float* r0 = res + (size_t)r * N + bn + wn * 4;
            const float4 ra = *(const float4*)(r0);
            const float4 rb = *(const float4*)(r0 + 64);
            v[0] += ra.x; v[1] += ra.y; v[2] += ra.z; v[3] += ra.w;
            v[4] += rb.x; v[5] += rb.y; v[6] += rb.z; v[7] += rb.w;
        }
        *(float4*)(c0)      = make_float4(v[0], v[1], v[2], v[3]);
        *(float4*)(c0 + 64) = make_float4(v[4], v[5], v[6], v[7]);
    }
}

// ---------------- fused attention (flash-style, fp32) ----------------
// One block per (b, h, 64-row q tile). 256 threads = 16x16 grid, 4x4 microtiles.
// Static 48KB smem: Q, K, V tiles of 64x64. The P tile ALIASES the K tile
// (K is dead after S = Q K^T); P uses an XOR-swizzled transposed layout so
// both its stores and its broadcast reads are bank-conflict-free.
__global__ __launch_bounds__(256)
void attn_kernel(const float* __restrict__ qkv, float* __restrict__ out) {
    __shared__ float Qst [64 * 64];  // [d][r]  d-major
    __shared__ float KPst[64 * 64];  // phase 1: K [d][c]; phase 2: P swizzled [k][r]
    __shared__ float Vs  [64 * 64];  // [k][d]  k-major

    const int b  = blockIdx.z;
    const int h  = blockIdx.y;
    const int q0 = blockIdx.x * 64;
    const int tid = threadIdx.x;
    const int tr = tid >> 4, tc = tid & 15;
    const int lr = tid >> 2, lc = tid & 3;
    const size_t base = (size_t)b * SEQ * QKVD + (size_t)h * HD;

    // load Q tile transposed, pre-scaled by 1/sqrt(hd)
    {
        const float* qrow = qkv + base + (size_t)(q0 + lr) * QKVD;
        #pragma unroll
        for (int c = 0; c < 4; c++) {
            const int d = lc * 16 + c * 4;
            const float4 v = *(const float4*)(qrow + d);
            Qst[(d + 0) * 64 + lr] = v.x * 0.125f;
            Qst[(d + 1) * 64 + lr] = v.y * 0.125f;
            Qst[(d + 2) * 64 + lr] = v.z * 0.125f;
            Qst[(d + 3) * 64 + lr] = v.w * 0.125f;
        }
    }

    float acc[4][4];
    #pragma unroll
    for (int i = 0; i < 4; i++)
        #pragma unroll
        for (int j = 0; j < 4; j++) acc[i][j] = 0.f;
    float m_i[4], l_i[4];
    #pragma unroll
    for (int i = 0; i < 4; i++) { m_i[i] = -1e30f; l_i[i] = 0.f; }

    for (int kt = 0; kt < SEQ; kt += 64) {
        __syncthreads();  // prev PV done reading KPst/Vs; Q visible (1st iter)
        {
            const float* krow = qkv + base + CDIM     + (size_t)(kt + lr) * QKVD;
            const float* vrow = qkv + base + 2 * CDIM + (size_t)(kt + lr) * QKVD;
            #pragma unroll
            for (int c = 0; c < 4; c++) {
                const int d = lc * 16 + c * 4;
                const float4 kv = *(const float4*)(krow + d);
                KPst[(d + 0) * 64 + lr] = kv.x;
                KPst[(d + 1) * 64 + lr] = kv.y;
                KPst[(d + 2) * 64 + lr] = kv.z;
                KPst[(d + 3) * 64 + lr] = kv.w;
                *(float4*)&Vs[lr * 64 + d] = *(const float4*)(vrow + d);
            }
        }
        __syncthreads();

        // S = Q K^T (scaled)
        float s[4][4];
        #pragma unroll
        for (int i = 0; i < 4; i++)
            #pragma unroll
            for (int j = 0; j < 4; j++) s[i][j] = 0.f;
        #pragma unroll
        for (int d = 0; d < 64; d++) {
            const float4 q = *(const float4*)&Qst [d * 64 + tr * 4];
            const float4 k = *(const float4*)&KPst[d * 64 + tc * 4];
            const float qa[4] = {q.x, q.y, q.z, q.w};
            const float ka[4] = {k.x, k.y, k.z, k.w};
            #pragma unroll
            for (int i = 0; i < 4; i++)
                #pragma unroll
                for (int j = 0; j < 4; j++)
                    s[i][j] += qa[i] * ka[j];
        }

        // online softmax across the 16 lanes owning each row (register-only)
        #pragma unroll
        for (int i = 0; i < 4; i++) {
            float mx = fmaxf(fmaxf(s[i][0], s[i][1]), fmaxf(s[i][2], s[i][3]));
            mx = fmaxf(mx, __shfl_xor_sync(0xffffffffu, mx, 1));
            mx = fmaxf(mx, __shfl_xor_sync(0xffffffffu, mx, 2));
            mx = fmaxf(mx, __shfl_xor_sync(0xffffffffu, mx, 4));
            mx = fmaxf(mx, __shfl_xor_sync(0xffffffffu, mx, 8));
            const float newm = fmaxf(m_i[i], mx);
            const float alpha = __expf(m_i[i] - newm);
            m_i[i] = newm;
            float rs = 0.f;
            #pragma unroll
            for (int j = 0; j < 4; j++) {
                const float p = __expf(s[i][j] - newm);
                s[i][j] = p;
                rs += p;
            }
            rs += __shfl_xor_sync(0xffffffffu, rs, 1);
            rs += __shfl_xor_sync(0xffffffffu, rs, 2);
            rs += __shfl_xor_sync(0xffffffffu, rs, 4);
            rs += __shfl_xor_sync(0xffffffffu, rs, 8);
            l_i[i] = l_i[i] * alpha + rs;
            #pragma unroll
            for (int j = 0; j < 4; j++) acc[i][j] *= alpha;
        }

        __syncthreads();  // all S reads of K done before P overwrites KPst

        // store P transposed into KPst with XOR swizzle:
        // float4 of 4 rows at  KPst[k*64 + ((tr*4) ^ (((k>>2)&7)*4))]
        // store: k = tc*4+j -> swizzle = (tc&7)*4 -> per-phase banks = tr^tc&7,
        // distinct across the 8 tc of each phase group -> conflict-free.
        #pragma unroll
        for (int j = 0; j < 4; j++) {
            const int k = tc * 4 + j;
            *(float4*)&KPst[k * 64 + ((tr * 4) ^ ((tc & 7) * 4))] =
                make_float4(s[0][j], s[1][j], s[2][j], s[3][j]);
        }
        __syncthreads();

        // O += P V   (P reads are per-row broadcast; swizzle recomputed)
        #pragma unroll
        for (int k = 0; k < 64; k++) {
            const float4 p = *(const float4*)
                &KPst[k * 64 + ((tr * 4) ^ (((k >> 2) & 7) * 4))];
            const float4 v = *(const float4*)&Vs[k * 64 + tc * 4];
            const float pa[4] = {p.x, p.y, p.z, p.w};
            const float va[4] = {v.x, v.y, v.z, v.w};
            #pragma unroll
            for (int i = 0; i < 4; i++)
                #pragma unroll
                for (int j = 0; j < 4; j++)
                    acc[i][j] += pa[i] * va[j];
        }
    }

    // epilogue: O /= l, write [b*SEQ+q0+r, h*HD + c]
    #pragma unroll
    for (int i = 0; i < 4; i++) {
        const float inv = 1.f / l_i[i];
        const size_t row = (size_t)(b * SEQ + q0 + tr * 4 + i);
        *(float4*)&out[row * CDIM + h * HD + tc * 4] =
            make_float4(acc[i][0] * inv, acc[i][1] * inv,
                        acc[i][2] * inv, acc[i][3] * inv);
    }
}

// ---------------- launch ----------------
extern "C" void kernel_launch(void* const* d_in, const int* in_sizes, int n_in,
                              void* d_out, int out_size) {
    const float* x      = (const float*)d_in[0];
    const float* w_qkv  = (const float*)d_in[1];
    const float* w_proj = (const float*)d_in[2];
    const float* b_proj = (const float*)d_in[3];
    const float* ln1_g  = (const float*)d_in[4];
    const float* ln1_b  = (const float*)d_in[5];
    const float* ln2_g  = (const float*)d_in[6];
    const float* ln2_b  = (const float*)d_in[7];
    const float* w_fc1  = (const float*)d_in[8];
    const float* b_fc1  = (const float*)d_in[9];
    const float* w_fc2  = (const float*)d_in[10];
    const float* b_fc2  = (const float*)d_in[11];
    float* out = (float*)d_out;

    float *y, *qkv, *att, *x1, *h, *f1;
    cudaGetSymbolAddress((void**)&y,   g_y);
    cudaGetSymbolAddress((void**)&qkv, g_qkv);
    cudaGetSymbolAddress((void**)&att, g_att);
    cudaGetSymbolAddress((void**)&x1,  g_x1);
    cudaGetSymbolAddress((void**)&h,   g_h);
    cudaGetSymbolAddress((void**)&f1,  g_f1);

    // 1) y = ln1(x)
    ln_kernel<<<MROWS, 256>>>(x, ln1_g, ln1_b, y);
    // 2) qkv = y @ w_qkv^T             [4096 x 3072 x 1024]
    gemm_nt<0><<<dim3(QKVD / 128, MROWS / 128), 256>>>(
        y, w_qkv, nullptr, nullptr, qkv, MROWS, QKVD, CDIM);
    // 3) att = softmax(q k^T / 8) v    (flash, per head)
    attn_kernel<<<dim3(SEQ / 64, NHEAD, 2), 256>>>(qkv, att);
    // 4) x1 = x + att @ w_proj^T + b_proj
    gemm_nt<2><<<dim3(CDIM / 128, MROWS / 128), 256>>>(
        att, w_proj, b_proj, x, x1, MROWS, CDIM, CDIM);
    // 5) h = ln2(x1)
    ln_kernel<<<MROWS, 256>>>(x1, ln2_g, ln2_b, h);
    // 6) f1 = gelu(h @ w_fc1^T + b_fc1)
    gemm_nt<1><<<dim3(HID / 128, MROWS / 128), 256>>>(
        h, w_fc1, b_fc1, nullptr, f1, MROWS, HID, CDIM);
    // 7) out = x1 + f1 @ w_fc2^T + b_fc2
    gemm_nt<2><<<dim3(CDIM / 128, MROWS / 128), 256>>>(
        f1, w_fc2, b_fc2, x1, out, MROWS, CDIM, HID);
}